// round 3
// baseline (speedup 1.0000x reference)
#include <cuda_runtime.h>
#include <cuda_bf16.h>
#include <cuda_fp16.h>
#include <cstdint>
#include <cstddef>

#define TBROWS 2048
#define VOC    50000
#define KDIM   512
#define SLEN   50
#define BATCH  32
#define EPSV   1e-10f
#define BM     128
#define BN     128
#define NKCH   8          // K chunks of 64 bf16 (128 B rows)
#define NTN    391        // ceil(50000/128)
#define CPG    9          // 16 x 9 = 144 CTAs = one wave
#define LN2F   0.69314718055994531f
#define STGPITCH 68       // uint32 pitch for epilogue staging (bank-conflict-free)

// ---------------- device scratch (static; no runtime allocation) ----------------
__device__ __align__(1024) __nv_bfloat16 g_Wb[(size_t)VOC * KDIM];     // 51.2 MB
__device__ __align__(1024) __nv_bfloat16 g_hb[(size_t)TBROWS * KDIM];  // 2 MB
__device__ __align__(1024) __half g_expl[(size_t)TBROWS * VOC];        // 200 MB exp(logit), col COPY zeroed
__device__ float  g_Zp[(size_t)TBROWS * NTN];  // per (row, n-tile) partial sum of exp
__device__ float  g_e0v[TBROWS];               // exp(logit[:,PAD])
__device__ float  g_copyv[TBROWS];             // sigmoid(logit[:,COPY])
__device__ int    g_fixc[TBROWS * SLEN];       // scatter cols (-1 = skip)
__device__ float  g_fixv[TBROWS * SLEN];       // scatter additive term (already /norm)
__device__ float2 g_rowp[TBROWS];              // {s1, padv}

// ---------------- PTX helpers (plain sm_103 target only!) ----------------
__device__ __forceinline__ uint32_t smem_u32(const void* p) {
    uint32_t a;
    asm("{ .reg .u64 t; cvta.to.shared.u64 t, %1; cvt.u32.u64 %0, t; }" : "=r"(a) : "l"(p));
    return a;
}
#define SWZ(x) ((x) ^ (((x) >> 3) & 0x70))

__device__ __forceinline__ void cp16(uint32_t dst, const void* src) {
    asm volatile("cp.async.cg.shared.global [%0], [%1], 16;" :: "r"(dst), "l"(src));
}
__device__ __forceinline__ void cp16z(uint32_t dst, const void* src, int okbytes) {
    asm volatile("cp.async.cg.shared.global [%0], [%1], 16, %2;"
                 :: "r"(dst), "l"(src), "r"(okbytes));
}
__device__ __forceinline__ void cp_commit() { asm volatile("cp.async.commit_group;"); }
__device__ __forceinline__ void cp_wait0()  { asm volatile("cp.async.wait_group 0;"); }
__device__ __forceinline__ void cp_wait1()  { asm volatile("cp.async.wait_group 1;"); }

__device__ __forceinline__ void ldsm4(uint32_t* r, uint32_t addr) {
    asm volatile("ldmatrix.sync.aligned.m8n8.x4.shared.b16 {%0,%1,%2,%3}, [%4];"
                 : "=r"(r[0]), "=r"(r[1]), "=r"(r[2]), "=r"(r[3]) : "r"(addr));
}
__device__ __forceinline__ void mma16816(float* d, const uint32_t* a, uint32_t b0, uint32_t b1) {
    asm volatile(
        "mma.sync.aligned.m16n8k16.row.col.f32.bf16.bf16.f32 "
        "{%0,%1,%2,%3}, {%4,%5,%6,%7}, {%8,%9}, {%0,%1,%2,%3};"
        : "+f"(d[0]), "+f"(d[1]), "+f"(d[2]), "+f"(d[3])
        : "r"(a[0]), "r"(a[1]), "r"(a[2]), "r"(a[3]), "r"(b0), "r"(b1));
}

// ---------------- kernel 1: fp32 -> bf16 conversion ----------------
__global__ void __launch_bounds__(256) prep_kernel(const float4* __restrict__ W4,
                                                   const float4* __restrict__ h4) {
    int i = blockIdx.x * 256 + threadIdx.x;
    const int WN = VOC * KDIM / 4;
    if (i < WN) {
        float4 v = W4[i];
        __nv_bfloat162 lo = __floats2bfloat162_rn(v.x, v.y);
        __nv_bfloat162 hi = __floats2bfloat162_rn(v.z, v.w);
        ((uint2*)g_Wb)[i] = make_uint2(*(uint32_t*)&lo, *(uint32_t*)&hi);
    }
    const int HN = TBROWS * KDIM / 4;
    if (i < HN) {
        float4 v = h4[i];
        __nv_bfloat162 lo = __floats2bfloat162_rn(v.x, v.y);
        __nv_bfloat162 hi = __floats2bfloat162_rn(v.z, v.w);
        ((uint2*)g_hb)[i] = make_uint2(*(uint32_t*)&lo, *(uint32_t*)&hi);
    }
}

// ---------------- kernel 2: mma.sync GEMM + exp epilogue ----------------
// Grid (16, CPG), 256 threads (8 warps, warp grid 4m x 2n, warp tile 32x64).
// A tile (128 x 512 bf16 = 128 KB) SMEM-resident; B double-buffered (2 x 16 KB).
__device__ __forceinline__ void loadB(int tid, int n0, int kk, uint32_t dst) {
#pragma unroll
    for (int i = 0; i < 4; i++) {
        int flat = i * 256 + tid;            // 1024 16B segments: 128 rows x 8 segs
        int r = flat >> 3, s = flat & 7;
        uint32_t off = SWZ((uint32_t)(r * 128 + s * 16));
        int gr = n0 + r;
        int ok = (gr < VOC) ? 16 : 0;
        const __nv_bfloat16* src =
            g_Wb + (size_t)((gr < VOC) ? gr : (VOC - 1)) * KDIM + kk * 64 + s * 8;
        cp16z(dst + off, src, ok);
    }
    cp_commit();
}

__global__ void __launch_bounds__(256, 1) gemm_kernel(const float* __restrict__ bias) {
    extern __shared__ char dsm[];
    __shared__ float s_bias[128];
    __shared__ float s_zrow[128];

    const int tid  = threadIdx.x;
    const int lane = tid & 31;
    const int wid  = tid >> 5;
    const int wm   = wid >> 1;       // 0..3
    const int wn   = wid & 1;        // 0..1
    const int m0   = blockIdx.x * BM;

    uint32_t sraw  = smem_u32(dsm);
    uint32_t aBase = (sraw + 1023u) & ~1023u;
    uint32_t pad   = aBase - sraw;
    uint32_t bBase = aBase + 131072u;              // 2 stages x 16 KB
    uint32_t* stg32 = (uint32_t*)(dsm + pad + 163840u);  // 128 x 68 uint32 staging

    // ---- load resident A: 8 chunks x (128 rows x 128 B), SW128 swizzled ----
#pragma unroll 4
    for (int it = 0; it < 32; it++) {
        int flat = it * 256 + tid;                 // 8192 segments
        int c = flat >> 10;
        int rem = flat & 1023;
        int r = rem >> 3, s = rem & 7;
        uint32_t off = (uint32_t)c * 16384u + SWZ((uint32_t)(r * 128 + s * 16));
        const __nv_bfloat16* src = g_hb + (size_t)(m0 + r) * KDIM + c * 64 + s * 8;
        cp16(aBase + off, src);
    }
    cp_commit();
    cp_wait0();
    if (tid < 128) s_zrow[tid] = 0.0f;
    __syncthreads();

    // ---- precompute swizzled ldmatrix offsets ----
    uint32_t aOff[2][4], bOff[4][4];
    {
        int rl = lane & 15;
        int kh = (lane >> 4) & 1;                  // 16B half of the 32B k16 strip
#pragma unroll
        for (int mi = 0; mi < 2; mi++) {
            int rowA = wm * 32 + mi * 16 + rl;
#pragma unroll
            for (int ks = 0; ks < 4; ks++)
                aOff[mi][ks] = SWZ((uint32_t)(rowA * 128 + ks * 32 + kh * 16));
        }
#pragma unroll
        for (int nf2 = 0; nf2 < 4; nf2++) {
            int rowB = wn * 64 + nf2 * 16 + rl;
#pragma unroll
            for (int ks = 0; ks < 4; ks++)
                bOff[nf2][ks] = SWZ((uint32_t)(rowB * 128 + ks * 32 + kh * 16));
        }
    }

    for (int j = blockIdx.y; j < NTN; j += CPG) {
        const int n0 = j * BN;
        if (tid < 128) s_bias[tid] = (n0 + tid < VOC) ? bias[n0 + tid] : 0.0f;

        float acc[2][8][4];
#pragma unroll
        for (int mi = 0; mi < 2; mi++)
#pragma unroll
            for (int nf = 0; nf < 8; nf++)
#pragma unroll
                for (int q = 0; q < 4; q++) acc[mi][nf][q] = 0.0f;

        loadB(tid, n0, 0, bBase);

        for (int kk = 0; kk < NKCH; kk++) {
            if (kk < NKCH - 1) {
                loadB(tid, n0, kk + 1, bBase + (uint32_t)((kk + 1) & 1) * 16384u);
                cp_wait1();
            } else {
                cp_wait0();
            }
            __syncthreads();

            uint32_t ab = aBase + (uint32_t)kk * 16384u;
            uint32_t bb = bBase + (uint32_t)(kk & 1) * 16384u;
#pragma unroll
            for (int ks = 0; ks < 4; ks++) {
                uint32_t a[2][4], b[4][4];
                ldsm4(a[0], ab + aOff[0][ks]);
                ldsm4(a[1], ab + aOff[1][ks]);
#pragma unroll
                for (int nf2 = 0; nf2 < 4; nf2++) ldsm4(b[nf2], bb + bOff[nf2][ks]);
#pragma unroll
                for (int mi = 0; mi < 2; mi++)
#pragma unroll
                    for (int nf2 = 0; nf2 < 4; nf2++) {
                        mma16816(acc[mi][nf2 * 2],     a[mi], b[nf2][0], b[nf2][2]);
                        mma16816(acc[mi][nf2 * 2 + 1], a[mi], b[nf2][1], b[nf2][3]);
                    }
            }
            __syncthreads();
        }

        // ---- epilogue: bias + exp + fp16 staging + per-row Z partials ----
        const int vrem = VOC - n0;
        const int rA0 = wm * 32 + (lane >> 2);
#pragma unroll
        for (int mi = 0; mi < 2; mi++) {
            const int rA = rA0 + mi * 16;
            const int rB = rA + 8;
            float sA = 0.0f, sB = 0.0f;
#pragma unroll
            for (int nf = 0; nf < 8; nf++) {
                const int cl = wn * 64 + nf * 8 + (lane & 3) * 2;
                const float bi0 = s_bias[cl], bi1 = s_bias[cl + 1];
                float lA0 = acc[mi][nf][0] + bi0, lA1 = acc[mi][nf][1] + bi1;
                float lB0 = acc[mi][nf][2] + bi0, lB1 = acc[mi][nf][3] + bi1;
                float eA0 = __expf(lA0), eA1 = __expf(lA1);
                float eB0 = __expf(lB0), eB1 = __expf(lB1);
                if (n0 == 0) {
                    if (cl == 0) { g_e0v[m0 + rA] = eA0; g_e0v[m0 + rB] = eB0; }
                    if (cl == 4) {
                        g_copyv[m0 + rA] = 1.0f / (1.0f + __expf(-lA0));
                        g_copyv[m0 + rB] = 1.0f / (1.0f + __expf(-lB0));
                        eA0 = 0.0f; eB0 = 0.0f;   // COPY masked from softmax
                    }
                }
                if (cl     >= vrem) { eA0 = 0.0f; eB0 = 0.0f; }
                if (cl + 1 >= vrem) { eA1 = 0.0f; eB1 = 0.0f; }
                sA += eA0 + eA1;  sB += eB0 + eB1;
                const int p = cl >> 1;
                __half2 hA = __floats2half2_rn(eA0, eA1);
                __half2 hB = __floats2half2_rn(eB0, eB1);
                stg32[rA * STGPITCH + p] = *(uint32_t*)&hA;
                stg32[rB * STGPITCH + p] = *(uint32_t*)&hB;
            }
            sA += __shfl_xor_sync(0xFFFFFFFFu, sA, 1);
            sA += __shfl_xor_sync(0xFFFFFFFFu, sA, 2);
            sB += __shfl_xor_sync(0xFFFFFFFFu, sB, 1);
            sB += __shfl_xor_sync(0xFFFFFFFFu, sB, 2);
            if ((lane & 3) == 0) {
                atomicAdd(&s_zrow[rA], sA);
                atomicAdd(&s_zrow[rB], sB);
            }
        }
        __syncthreads();

        // coalesced copy-out: rows of 128 halves (16 x uint4), tail tile: 80 halves (10)
        const int segs = (vrem >= 128) ? 16 : 10;
#pragma unroll 4
        for (int f = tid; f < 2048; f += 256) {
            int r = f >> 4, s = f & 15;
            if (s < segs) {
                uint4 v = *(uint4*)(stg32 + r * STGPITCH + s * 4);
                ((uint4*)(g_expl + (size_t)(m0 + r) * VOC + n0))[s] = v;
            }
        }
        if (tid < 128) {
            g_Zp[(size_t)(m0 + tid) * NTN + j] = s_zrow[tid];
            s_zrow[tid] = 0.0f;
        }
        __syncthreads();
    }
}

// ---------------- kernel 3: per-row params (Z, norm, scatter dedup) ----------------
__global__ void __launch_bounds__(64) rowparams_kernel(const float* __restrict__ attn,
                                                       const int* __restrict__ src,
                                                       const int* __restrict__ alignment) {
    __shared__ float s_red[64];
    __shared__ float s_attn[SLEN];
    __shared__ int   s_idx[SLEN];
    __shared__ float s_c, s_norm;

    const int r = blockIdx.x, t = threadIdx.x;
    float z = 0.0f;
    for (int j = t; j < NTN; j += 64) z += g_Zp[(size_t)r * NTN + j];
    s_red[t] = z;
    __syncthreads();
    for (int o = 32; o > 0; o >>= 1) {
        if (t < o) s_red[t] += s_red[t + o];
        __syncthreads();
    }
    if (t < SLEN) {
        s_attn[t] = attn[r * SLEN + t];
        int bb = r % BATCH;
        s_idx[t] = alignment[src[bb * SLEN + t]];
    }
    __syncthreads();
    if (t == 0) {
        float Z  = s_red[0];
        float c  = g_copyv[r];
        float e0 = g_e0v[r];
        float sa = 0.0f, A0 = 0.0f;
        for (int s = 0; s < SLEN; s++) {
            sa += s_attn[s];
            if (s_idx[s] == 0) A0 += s_attn[s];
        }
        float norm = EPSV + (1.0f - c) * (1.0f - e0 / Z) + c * (sa - A0);
        s_c = c; s_norm = norm;
        float s1 = (1.0f - c) / (Z * norm);
        float padv = logf(EPSV / norm + EPSV);
        g_rowp[r] = make_float2(s1, padv);
    }
    __syncthreads();
    if (t < SLEN) {
        int idx = s_idx[t];
        int owner = (idx != 0);
        float sum = 0.0f;
        for (int s = 0; s < SLEN; s++) {
            if (s_idx[s] == idx) {
                if (s < t) owner = 0;
                sum += s_attn[s];
            }
        }
        if (owner) {
            g_fixc[r * SLEN + t] = idx;
            g_fixv[r * SLEN + t] = s_c * sum / s_norm;
        } else {
            g_fixc[r * SLEN + t] = -1;
        }
    }
}

// ---------------- kernel 4: final log output + scatter fix-ups ----------------
__global__ void __launch_bounds__(512) final_kernel(float* __restrict__ out) {
    const int r = blockIdx.x;
    const float2 rp = g_rowp[r];
    const float s1 = rp.x;
    const uint32_t* ep = (const uint32_t*)(g_expl + (size_t)r * VOC);
    float2* o2 = (float2*)(out + (size_t)r * VOC);

    for (int p = threadIdx.x; p < VOC / 2; p += 512) {
        uint32_t pk = ep[p];
        __half2 h2 = *(__half2*)&pk;
        float v0 = fmaf(__half2float(h2.x), s1, EPSV);
        float v1 = fmaf(__half2float(h2.y), s1, EPSV);
        o2[p] = make_float2(LN2F * __log2f(v0), LN2F * __log2f(v1));
    }
    __syncthreads();
    const int t = threadIdx.x;
    if (t < SLEN) {
        int cidx = g_fixc[r * SLEN + t];
        if (cidx >= 0) {
            float e = __half2float(g_expl[(size_t)r * VOC + cidx]);
            float v = fmaf(e, s1, g_fixv[r * SLEN + t] + EPSV);
            out[(size_t)r * VOC + cidx] = LN2F * __log2f(v);
        }
    } else if (t == SLEN) {
        out[(size_t)r * VOC] = rp.y;  // PAD column
    }
}

// ---------------- launch ----------------
extern "C" void kernel_launch(void* const* d_in, const int* in_sizes, int n_in,
                              void* d_out, int out_size) {
    const float* hidden    = (const float*)d_in[0];
    const float* attn      = (const float*)d_in[1];
    const float* W         = (const float*)d_in[2];
    const float* b         = (const float*)d_in[3];
    const int*   src       = (const int*)d_in[4];
    const int*   alignment = (const int*)d_in[5];
    float* out = (float*)d_out;

    // A(128K) + B(32K) + staging(34K) + alignment pad
    const int dyn_smem = 1024 + 131072 + 32768 + 34816;
    cudaFuncSetAttribute(gemm_kernel, cudaFuncAttributeMaxDynamicSharedMemorySize, dyn_smem);

    prep_kernel<<<25000, 256>>>((const float4*)W, (const float4*)hidden);
    gemm_kernel<<<dim3(16, CPG), 256, dyn_smem>>>(b);
    rowparams_kernel<<<TBROWS, 64>>>(attn, src, alignment);
    final_kernel<<<TBROWS, 512>>>(out);
}

// round 4
// speedup vs baseline: 1.1383x; 1.1383x over previous
#include <cuda_runtime.h>
#include <cuda_bf16.h>
#include <cuda_fp16.h>
#include <cstdint>
#include <cstddef>

#define TBROWS 2048
#define VOC    50000
#define KDIM   512
#define SLEN   50
#define BATCH  32
#define EPSV   1e-10f
#define BM     128
#define BN     128
#define NKCH   8          // K chunks of 64 bf16 (128 B rows)
#define NTN    391        // ceil(50000/128)
#define CPG    9          // 16 x 9 = 144 CTAs = one wave
#define STGPITCH 68       // uint32 pitch for epilogue staging (bank-conflict-free)
#define LOG_EPS (-23.025850929940457f)

// ---------------- device scratch (static; no runtime allocation) ----------------
__device__ __align__(1024) __nv_bfloat16 g_Wb[(size_t)VOC * KDIM];     // 51.2 MB
__device__ __align__(1024) __nv_bfloat16 g_hb[(size_t)TBROWS * KDIM];  // 2 MB
__device__ __align__(1024) __half g_logit[(size_t)TBROWS * VOC];       // 200 MB fp16 LOGITS
__device__ float  g_Zp[(size_t)TBROWS * NTN];  // per (row, n-tile) partial sum of exp
__device__ float  g_e0v[TBROWS];               // exp(logit[:,PAD])
__device__ float  g_copyv[TBROWS];             // sigmoid(logit[:,COPY])
__device__ int    g_fixc[TBROWS * SLEN];       // scatter cols (-1 = skip)
__device__ float  g_fixv[TBROWS * SLEN];       // scatter additive term (already /norm)
__device__ float4 g_rowp[TBROWS];              // {s1, padv, log(s1), unused}

// ---------------- PTX helpers (plain sm_103 target only) ----------------
__device__ __forceinline__ uint32_t smem_u32(const void* p) {
    uint32_t a;
    asm("{ .reg .u64 t; cvta.to.shared.u64 t, %1; cvt.u32.u64 %0, t; }" : "=r"(a) : "l"(p));
    return a;
}
#define SWZ(x) ((x) ^ (((x) >> 3) & 0x70))

__device__ __forceinline__ void cp16(uint32_t dst, const void* src) {
    asm volatile("cp.async.cg.shared.global [%0], [%1], 16;" :: "r"(dst), "l"(src));
}
__device__ __forceinline__ void cp16z(uint32_t dst, const void* src, int okbytes) {
    asm volatile("cp.async.cg.shared.global [%0], [%1], 16, %2;"
                 :: "r"(dst), "l"(src), "r"(okbytes));
}
__device__ __forceinline__ void cp_commit() { asm volatile("cp.async.commit_group;"); }
__device__ __forceinline__ void cp_wait0()  { asm volatile("cp.async.wait_group 0;"); }
__device__ __forceinline__ void cp_wait1()  { asm volatile("cp.async.wait_group 1;"); }

__device__ __forceinline__ void ldsm4(uint32_t* r, uint32_t addr) {
    asm volatile("ldmatrix.sync.aligned.m8n8.x4.shared.b16 {%0,%1,%2,%3}, [%4];"
                 : "=r"(r[0]), "=r"(r[1]), "=r"(r[2]), "=r"(r[3]) : "r"(addr));
}
__device__ __forceinline__ void mma16816(float* d, const uint32_t* a, uint32_t b0, uint32_t b1) {
    asm volatile(
        "mma.sync.aligned.m16n8k16.row.col.f32.bf16.bf16.f32 "
        "{%0,%1,%2,%3}, {%4,%5,%6,%7}, {%8,%9}, {%0,%1,%2,%3};"
        : "+f"(d[0]), "+f"(d[1]), "+f"(d[2]), "+f"(d[3])
        : "r"(a[0]), "r"(a[1]), "r"(a[2]), "r"(a[3]), "r"(b0), "r"(b1));
}

// FMA/ALU-pipe exp (Taylor deg-4 for 2^f, rel err < 5e-5) — runs parallel to MUFU.
__device__ __forceinline__ float pexp(float x) {
    float y = x * 1.4426950408889634f;
    float r = __fadd_rn(y, 12582912.0f);          // round-to-nearest int in mantissa
    int   i = __float_as_int(r) - 0x4B400000;
    float f = __fsub_rn(y, __fsub_rn(r, 12582912.0f));   // f in [-0.5, 0.5]
    float p = fmaf(f, 0.00961813f, 0.05550411f);
    p = fmaf(f, p, 0.24022651f);
    p = fmaf(f, p, 0.69314718f);
    p = fmaf(f, p, 1.0f);
    return __int_as_float(__float_as_int(p) + (i << 23));
}

// ---------------- kernel 1: fp32 -> bf16 conversion ----------------
__global__ void __launch_bounds__(256) prep_kernel(const float4* __restrict__ W4,
                                                   const float4* __restrict__ h4) {
    int i = blockIdx.x * 256 + threadIdx.x;
    const int WN = VOC * KDIM / 4;
    if (i < WN) {
        float4 v = W4[i];
        __nv_bfloat162 lo = __floats2bfloat162_rn(v.x, v.y);
        __nv_bfloat162 hi = __floats2bfloat162_rn(v.z, v.w);
        ((uint2*)g_Wb)[i] = make_uint2(*(uint32_t*)&lo, *(uint32_t*)&hi);
    }
    const int HN = TBROWS * KDIM / 4;
    if (i < HN) {
        float4 v = h4[i];
        __nv_bfloat162 lo = __floats2bfloat162_rn(v.x, v.y);
        __nv_bfloat162 hi = __floats2bfloat162_rn(v.z, v.w);
        ((uint2*)g_hb)[i] = make_uint2(*(uint32_t*)&lo, *(uint32_t*)&hi);
    }
}

// ---------------- kernel 2: mma.sync GEMM + exp epilogue ----------------
// Grid (16, CPG), 512 threads (16 warps, warp grid 4m x 4n, warp tile 32x32).
// A (128 x 512 bf16 = 128 KB) SMEM-resident; B double-buffered (2 x 16 KB).
__device__ __forceinline__ void loadB(int tid, int n0, int kk, uint32_t dst) {
#pragma unroll
    for (int i = 0; i < 2; i++) {
        int flat = i * 512 + tid;            // 1024 16B segments: 128 rows x 8 segs
        int r = flat >> 3, s = flat & 7;
        uint32_t off = SWZ((uint32_t)(r * 128 + s * 16));
        int gr = n0 + r;
        int ok = (gr < VOC) ? 16 : 0;
        const __nv_bfloat16* src =
            g_Wb + (size_t)((gr < VOC) ? gr : (VOC - 1)) * KDIM + kk * 64 + s * 8;
        cp16z(dst + off, src, ok);
    }
    cp_commit();
}

__global__ void __launch_bounds__(512, 1) gemm_kernel(const float* __restrict__ bias) {
    extern __shared__ char dsm[];
    __shared__ float s_bias[128];
    __shared__ float s_zrow[128];

    const int tid  = threadIdx.x;
    const int lane = tid & 31;
    const int wid  = tid >> 5;
    const int wm   = wid >> 2;       // 0..3
    const int wn   = wid & 3;        // 0..3
    const int m0   = blockIdx.x * BM;

    uint32_t sraw  = smem_u32(dsm);
    uint32_t aBase = (sraw + 1023u) & ~1023u;
    uint32_t pad   = aBase - sraw;
    uint32_t bBase = aBase + 131072u;                    // 2 stages x 16 KB
    uint32_t* stg32 = (uint32_t*)(dsm + pad + 163840u);  // 128 x 68 uint32 staging

    // ---- load resident A: 8 chunks x (128 rows x 128 B), SW128 swizzled ----
#pragma unroll 4
    for (int it = 0; it < 16; it++) {
        int flat = it * 512 + tid;                       // 8192 segments
        int c = flat >> 10;
        int rem = flat & 1023;
        int r = rem >> 3, s = rem & 7;
        uint32_t off = (uint32_t)c * 16384u + SWZ((uint32_t)(r * 128 + s * 16));
        const __nv_bfloat16* src = g_hb + (size_t)(m0 + r) * KDIM + c * 64 + s * 8;
        cp16(aBase + off, src);
    }
    cp_commit();
    // prefetch first tile's chunk 0 into stage 0
    loadB(tid, blockIdx.y * BN, 0, bBase);
    cp_wait1();                                          // A resident complete
    if (tid < 128) s_zrow[tid] = 0.0f;
    __syncthreads();

    // ---- precompute swizzled ldmatrix offsets ----
    uint32_t aOff[2][4], bOff[2][4];
    {
        int rl = lane & 15;
        int kh = (lane >> 4) & 1;
#pragma unroll
        for (int mi = 0; mi < 2; mi++) {
            int rowA = wm * 32 + mi * 16 + rl;
#pragma unroll
            for (int ks = 0; ks < 4; ks++)
                aOff[mi][ks] = SWZ((uint32_t)(rowA * 128 + ks * 32 + kh * 16));
        }
#pragma unroll
        for (int nf2 = 0; nf2 < 2; nf2++) {
            int rowB = wn * 32 + nf2 * 16 + rl;
#pragma unroll
            for (int ks = 0; ks < 4; ks++)
                bOff[nf2][ks] = SWZ((uint32_t)(rowB * 128 + ks * 32 + kh * 16));
        }
    }

    for (int j = blockIdx.y; j < NTN; j += CPG) {
        const int n0 = j * BN;
        if (tid < 128) s_bias[tid] = (n0 + tid < VOC) ? bias[n0 + tid] : 0.0f;

        float acc[2][4][4];
#pragma unroll
        for (int mi = 0; mi < 2; mi++)
#pragma unroll
            for (int nf = 0; nf < 4; nf++)
#pragma unroll
                for (int q = 0; q < 4; q++) acc[mi][nf][q] = 0.0f;

        // chunk 0 already prefetched into stage 0
        for (int kk = 0; kk < NKCH; kk++) {
            if (kk < NKCH - 1) {
                loadB(tid, n0, kk + 1, bBase + (uint32_t)((kk + 1) & 1) * 16384u);
                cp_wait1();
            } else {
                cp_wait0();
            }
            __syncthreads();

            uint32_t ab = aBase + (uint32_t)kk * 16384u;
            uint32_t bb = bBase + (uint32_t)(kk & 1) * 16384u;
#pragma unroll
            for (int ks = 0; ks < 4; ks++) {
                uint32_t a[2][4], b[2][4];
                ldsm4(a[0], ab + aOff[0][ks]);
                ldsm4(a[1], ab + aOff[1][ks]);
                ldsm4(b[0], bb + bOff[0][ks]);
                ldsm4(b[1], bb + bOff[1][ks]);
#pragma unroll
                for (int mi = 0; mi < 2; mi++)
#pragma unroll
                    for (int nf2 = 0; nf2 < 2; nf2++) {
                        mma16816(acc[mi][nf2 * 2],     a[mi], b[nf2][0], b[nf2][2]);
                        mma16816(acc[mi][nf2 * 2 + 1], a[mi], b[nf2][1], b[nf2][3]);
                    }
            }
            __syncthreads();
        }

        // prefetch next tile's chunk 0 (overlaps the exp-heavy epilogue)
        if (j + CPG < NTN) loadB(tid, (j + CPG) * BN, 0, bBase);

        // ---- epilogue: bias add, exp for Z (split MUFU/FMA), fp16 logit staging ----
        const int vrem = VOC - n0;
        const int rA0 = wm * 32 + (lane >> 2);
#pragma unroll
        for (int mi = 0; mi < 2; mi++) {
            const int rA = rA0 + mi * 16;
            const int rB = rA + 8;
            float sA = 0.0f, sB = 0.0f;
#pragma unroll
            for (int nf = 0; nf < 4; nf++) {
                const int cl = wn * 32 + nf * 8 + (lane & 3) * 2;
                const float bi0 = s_bias[cl], bi1 = s_bias[cl + 1];
                float lA0 = acc[mi][nf][0] + bi0, lA1 = acc[mi][nf][1] + bi1;
                float lB0 = acc[mi][nf][2] + bi0, lB1 = acc[mi][nf][3] + bi1;
                float eA0 = __expf(lA0), eA1 = pexp(lA1);   // split pipes
                float eB0 = __expf(lB0), eB1 = pexp(lB1);
                if (n0 == 0) {
                    if (cl == 0) { g_e0v[m0 + rA] = eA0; g_e0v[m0 + rB] = eB0; }
                    if (cl == 4) {
                        g_copyv[m0 + rA] = 1.0f / (1.0f + __expf(-lA0));
                        g_copyv[m0 + rB] = 1.0f / (1.0f + __expf(-lB0));
                        eA0 = 0.0f; eB0 = 0.0f;             // COPY masked from softmax
                    }
                }
                if (cl     >= vrem) { eA0 = 0.0f; eB0 = 0.0f; }
                if (cl + 1 >= vrem) { eA1 = 0.0f; eB1 = 0.0f; }
                sA += eA0 + eA1;  sB += eB0 + eB1;
                const int p = cl >> 1;
                __half2 hA = __floats2half2_rn(lA0, lA1);   // store LOGITS
                __half2 hB = __floats2half2_rn(lB0, lB1);
                stg32[rA * STGPITCH + p] = *(uint32_t*)&hA;
                stg32[rB * STGPITCH + p] = *(uint32_t*)&hB;
            }
            sA += __shfl_xor_sync(0xFFFFFFFFu, sA, 1);
            sA += __shfl_xor_sync(0xFFFFFFFFu, sA, 2);
            sB += __shfl_xor_sync(0xFFFFFFFFu, sB, 1);
            sB += __shfl_xor_sync(0xFFFFFFFFu, sB, 2);
            if ((lane & 3) == 0) {
                atomicAdd(&s_zrow[rA], sA);
                atomicAdd(&s_zrow[rB], sB);
            }
        }
        __syncthreads();

        // coalesced copy-out: 128 rows x 16 uint4 (tail tile: 10 = 80 halves)
        const int segs = (vrem >= 128) ? 16 : 10;
#pragma unroll
        for (int f = tid; f < 2048; f += 512) {
            int r = f >> 4, s = f & 15;
            if (s < segs) {
                uint4 v = *(uint4*)(stg32 + r * STGPITCH + s * 4);
                ((uint4*)(g_logit + (size_t)(m0 + r) * VOC + n0))[s] = v;
            }
        }
        if (tid < 128) {
            g_Zp[(size_t)(m0 + tid) * NTN + j] = s_zrow[tid];
            s_zrow[tid] = 0.0f;
        }
        __syncthreads();
    }
}

// ---------------- kernel 3: per-row params (Z, norm, scatter dedup) ----------------
__global__ void __launch_bounds__(64) rowparams_kernel(const float* __restrict__ attn,
                                                       const int* __restrict__ src,
                                                       const int* __restrict__ alignment) {
    __shared__ float s_red[64];
    __shared__ float s_attn[SLEN];
    __shared__ int   s_idx[SLEN];
    __shared__ float s_c, s_norm;

    const int r = blockIdx.x, t = threadIdx.x;
    float z = 0.0f;
    for (int j = t; j < NTN; j += 64) z += g_Zp[(size_t)r * NTN + j];
    s_red[t] = z;
    __syncthreads();
    for (int o = 32; o > 0; o >>= 1) {
        if (t < o) s_red[t] += s_red[t + o];
        __syncthreads();
    }
    if (t < SLEN) {
        s_attn[t] = attn[r * SLEN + t];
        int bb = r % BATCH;
        s_idx[t] = alignment[src[bb * SLEN + t]];
    }
    __syncthreads();
    if (t == 0) {
        float Z  = s_red[0];
        float c  = g_copyv[r];
        float e0 = g_e0v[r];
        float sa = 0.0f, A0 = 0.0f;
        for (int s = 0; s < SLEN; s++) {
            sa += s_attn[s];
            if (s_idx[s] == 0) A0 += s_attn[s];
        }
        float norm = EPSV + (1.0f - c) * (1.0f - e0 / Z) + c * (sa - A0);
        s_c = c; s_norm = norm;
        float s1 = (1.0f - c) / (Z * norm);
        float padv = logf(EPSV / norm + EPSV);
        g_rowp[r] = make_float4(s1, padv, logf(s1), 0.0f);
    }
    __syncthreads();
    if (t < SLEN) {
        int idx = s_idx[t];
        int owner = (idx != 0);
        float sum = 0.0f;
        for (int s = 0; s < SLEN; s++) {
            if (s_idx[s] == idx) {
                if (s < t) owner = 0;
                sum += s_attn[s];
            }
        }
        if (owner) {
            g_fixc[r * SLEN + t] = idx;
            g_fixv[r * SLEN + t] = s_c * sum / s_norm;
        } else {
            g_fixc[r * SLEN + t] = -1;
        }
    }
}

// ---------------- kernel 4: final output (pure streaming add) + fix-ups ----------------
__global__ void __launch_bounds__(512) final_kernel(float* __restrict__ out) {
    const int r = blockIdx.x;
    const float4 rp = g_rowp[r];
    const float C = rp.z;                        // log(s1)
    const size_t base = (size_t)r * VOC;
    const uint2* ep = (const uint2*)(g_logit + base);   // 4 halves per load
    float4* o4 = (float4*)(out + base);

    for (int p = threadIdx.x; p < VOC / 4; p += 512) {
        uint2 pk = __ldcs(&ep[p]);
        __half2 h0 = *(__half2*)&pk.x, h1 = *(__half2*)&pk.y;
        float2 f0 = __half22float2(h0), f1 = __half22float2(h1);
        float4 v = make_float4(f0.x + C, f0.y + C, f1.x + C, f1.y + C);
        __stcs(&o4[p], v);
    }
    __syncthreads();
    const int t = threadIdx.x;
    if (t == 0) out[base + 4] = LOG_EPS;         // COPY default (overwritten if scattered)
    if (t == 1) out[base + 0] = rp.y;            // PAD
    __syncthreads();
    if (t < SLEN) {
        int cidx = g_fixc[r * SLEN + t];
        if (cidx >= 0) {
            float l = __half2float(g_logit[base + cidx]);
            float e = (cidx == 4) ? 0.0f : __expf(l);
            float v = fmaf(e, rp.x, g_fixv[r * SLEN + t] + EPSV);
            out[base + cidx] = logf(v);
        }
    }
}

// ---------------- launch ----------------
extern "C" void kernel_launch(void* const* d_in, const int* in_sizes, int n_in,
                              void* d_out, int out_size) {
    const float* hidden    = (const float*)d_in[0];
    const float* attn      = (const float*)d_in[1];
    const float* W         = (const float*)d_in[2];
    const float* b         = (const float*)d_in[3];
    const int*   src       = (const int*)d_in[4];
    const int*   alignment = (const int*)d_in[5];
    float* out = (float*)d_out;

    // pad(1K) + A(128K) + B(32K) + staging(34K)
    const int dyn_smem = 1024 + 131072 + 32768 + 34816;
    cudaFuncSetAttribute(gemm_kernel, cudaFuncAttributeMaxDynamicSharedMemorySize, dyn_smem);

    prep_kernel<<<25000, 256>>>((const float4*)W, (const float4*)hidden);
    gemm_kernel<<<dim3(16, CPG), 512, dyn_smem>>>(b);
    rowparams_kernel<<<TBROWS, 64>>>(attn, src, alignment);
    final_kernel<<<TBROWS, 512>>>(out);
}

// round 5
// speedup vs baseline: 1.2886x; 1.1321x over previous
#include <cuda_runtime.h>
#include <cuda_bf16.h>
#include <cuda_fp16.h>
#include <cstdint>
#include <cstddef>

#define TBROWS 2048
#define VOC    50000
#define KDIM   512
#define SLEN   50
#define BATCH  32
#define EPSV   1e-10f
#define BM     128
#define BN     128
#define NKCH   8          // K chunks of 64 bf16 (128 B rows)
#define NTN    391        // ceil(50000/128)
#define NTILES (16 * NTN) // 6256 flattened tiles
#define NCTA   296        // 2 CTAs/SM x 148 SMs
#define STGPITCH 68       // uint32 pitch for epilogue staging (bank-conflict-free)
#define LOG_EPS (-23.025850929940457f)

// ---------------- device scratch (static; no runtime allocation) ----------------
__device__ __align__(1024) __nv_bfloat16 g_Wb[(size_t)VOC * KDIM];     // 51.2 MB
__device__ __align__(1024) __nv_bfloat16 g_hb[(size_t)TBROWS * KDIM];  // 2 MB (L2-resident)
__device__ __align__(1024) __half g_logit[(size_t)TBROWS * VOC];       // 200 MB fp16 LOGITS
__device__ float  g_Zp[(size_t)TBROWS * NTN];  // per (row, n-tile) partial sum of exp
__device__ float  g_e0v[TBROWS];               // exp(logit[:,PAD])
__device__ float  g_copyv[TBROWS];             // sigmoid(logit[:,COPY])
__device__ int    g_fixc[TBROWS * SLEN];       // scatter cols (-1 = skip)
__device__ float  g_fixv[TBROWS * SLEN];       // scatter additive term (already /norm)
__device__ float4 g_rowp[TBROWS];              // {s1, padv, log(s1), unused}

// ---------------- PTX helpers (plain sm_103 target only) ----------------
__device__ __forceinline__ uint32_t smem_u32(const void* p) {
    uint32_t a;
    asm("{ .reg .u64 t; cvta.to.shared.u64 t, %1; cvt.u32.u64 %0, t; }" : "=r"(a) : "l"(p));
    return a;
}
#define SWZ(x) ((x) ^ (((x) >> 3) & 0x70))

__device__ __forceinline__ void cp16(uint32_t dst, const void* src) {
    asm volatile("cp.async.cg.shared.global [%0], [%1], 16;" :: "r"(dst), "l"(src));
}
__device__ __forceinline__ void cp16z(uint32_t dst, const void* src, int okbytes) {
    asm volatile("cp.async.cg.shared.global [%0], [%1], 16, %2;"
                 :: "r"(dst), "l"(src), "r"(okbytes));
}
__device__ __forceinline__ void cp_commit() { asm volatile("cp.async.commit_group;"); }
__device__ __forceinline__ void cp_wait0()  { asm volatile("cp.async.wait_group 0;"); }
__device__ __forceinline__ void cp_wait1()  { asm volatile("cp.async.wait_group 1;"); }

__device__ __forceinline__ void ldsm4(uint32_t* r, uint32_t addr) {
    asm volatile("ldmatrix.sync.aligned.m8n8.x4.shared.b16 {%0,%1,%2,%3}, [%4];"
                 : "=r"(r[0]), "=r"(r[1]), "=r"(r[2]), "=r"(r[3]) : "r"(addr));
}
__device__ __forceinline__ void mma16816(float* d, const uint32_t* a, uint32_t b0, uint32_t b1) {
    asm volatile(
        "mma.sync.aligned.m16n8k16.row.col.f32.bf16.bf16.f32 "
        "{%0,%1,%2,%3}, {%4,%5,%6,%7}, {%8,%9}, {%0,%1,%2,%3};"
        : "+f"(d[0]), "+f"(d[1]), "+f"(d[2]), "+f"(d[3])
        : "r"(a[0]), "r"(a[1]), "r"(a[2]), "r"(a[3]), "r"(b0), "r"(b1));
}

// FMA/ALU-pipe exp (deg-4 2^f, rel err < 5e-5) — runs parallel to MUFU.
__device__ __forceinline__ float pexp(float x) {
    float y = x * 1.4426950408889634f;
    float r = __fadd_rn(y, 12582912.0f);
    int   i = __float_as_int(r) - 0x4B400000;
    float f = __fsub_rn(y, __fsub_rn(r, 12582912.0f));
    float p = fmaf(f, 0.00961813f, 0.05550411f);
    p = fmaf(f, p, 0.24022651f);
    p = fmaf(f, p, 0.69314718f);
    p = fmaf(f, p, 1.0f);
    return __int_as_float(__float_as_int(p) + (i << 23));
}

// ---------------- kernel 1: fp32 -> bf16 conversion ----------------
__global__ void __launch_bounds__(256) prep_kernel(const float4* __restrict__ W4,
                                                   const float4* __restrict__ h4) {
    int i = blockIdx.x * 256 + threadIdx.x;
    const int WN = VOC * KDIM / 4;
    if (i < WN) {
        float4 v = W4[i];
        __nv_bfloat162 lo = __floats2bfloat162_rn(v.x, v.y);
        __nv_bfloat162 hi = __floats2bfloat162_rn(v.z, v.w);
        ((uint2*)g_Wb)[i] = make_uint2(*(uint32_t*)&lo, *(uint32_t*)&hi);
    }
    const int HN = TBROWS * KDIM / 4;
    if (i < HN) {
        float4 v = h4[i];
        __nv_bfloat162 lo = __floats2bfloat162_rn(v.x, v.y);
        __nv_bfloat162 hi = __floats2bfloat162_rn(v.z, v.w);
        ((uint2*)g_hb)[i] = make_uint2(*(uint32_t*)&lo, *(uint32_t*)&hi);
    }
}

// ---------------- kernel 2: mma.sync GEMM + exp epilogue (2 CTAs/SM) ----------------
// 296 persistent CTAs, 256 threads (8 warps, warp grid 4m x 2n, warp tile 32x64).
// A and B both streamed, 2-stage double buffer each (16 KB/stage).
__device__ __forceinline__ void loadChunk(int tid, int m0, int n0, int kk,
                                          uint32_t aDst, uint32_t bDst) {
#pragma unroll
    for (int i = 0; i < 4; i++) {                 // A: 1024 x 16B segs
        int flat = i * 256 + tid;
        int r = flat >> 3, s = flat & 7;
        uint32_t off = SWZ((uint32_t)(r * 128 + s * 16));
        cp16(aDst + off, g_hb + (size_t)(m0 + r) * KDIM + kk * 64 + s * 8);
    }
#pragma unroll
    for (int i = 0; i < 4; i++) {                 // B: 1024 x 16B segs
        int flat = i * 256 + tid;
        int r = flat >> 3, s = flat & 7;
        uint32_t off = SWZ((uint32_t)(r * 128 + s * 16));
        int gr = n0 + r;
        int ok = (gr < VOC) ? 16 : 0;
        cp16z(bDst + off,
              g_Wb + (size_t)((gr < VOC) ? gr : (VOC - 1)) * KDIM + kk * 64 + s * 8, ok);
    }
    cp_commit();
}

__global__ void __launch_bounds__(256, 2) gemm_kernel(const float* __restrict__ bias) {
    extern __shared__ char dsm[];
    __shared__ float s_bias[128];
    __shared__ float s_zrow[128];

    const int tid  = threadIdx.x;
    const int lane = tid & 31;
    const int wid  = tid >> 5;
    const int wm   = wid >> 1;       // 0..3
    const int wn   = wid & 1;        // 0..1

    uint32_t sraw  = smem_u32(dsm);
    uint32_t aBase = (sraw + 1023u) & ~1023u;
    uint32_t pad   = aBase - sraw;
    uint32_t aS[2] = { aBase,          aBase + 16384u };
    uint32_t bS[2] = { aBase + 32768u, aBase + 49152u };
    uint32_t* stg32 = (uint32_t*)(dsm + pad + 65536u);   // 128 x 68 uint32 staging

    // ---- precompute swizzled ldmatrix offsets ----
    uint32_t aOff[2][4], bOff[4][4];
    {
        int rl = lane & 15;
        int kh = (lane >> 4) & 1;
#pragma unroll
        for (int mi = 0; mi < 2; mi++) {
            int rowA = wm * 32 + mi * 16 + rl;
#pragma unroll
            for (int ks = 0; ks < 4; ks++)
                aOff[mi][ks] = SWZ((uint32_t)(rowA * 128 + ks * 32 + kh * 16));
        }
#pragma unroll
        for (int nf2 = 0; nf2 < 4; nf2++) {
            int rowB = wn * 64 + nf2 * 16 + rl;
#pragma unroll
            for (int ks = 0; ks < 4; ks++)
                bOff[nf2][ks] = SWZ((uint32_t)(rowB * 128 + ks * 32 + kh * 16));
        }
    }

    if (tid < 128) s_zrow[tid] = 0.0f;

    int tile = blockIdx.x;
    if (tile < NTILES)
        loadChunk(tid, (tile & 15) * BM, (tile >> 4) * BN, 0, aS[0], bS[0]);

    for (; tile < NTILES; tile += NCTA) {
        const int m0 = (tile & 15) * BM;
        const int j  = tile >> 4;
        const int n0 = j * BN;
        if (tid < 128) s_bias[tid] = (n0 + tid < VOC) ? bias[n0 + tid] : 0.0f;

        float acc[2][8][4];
#pragma unroll
        for (int mi = 0; mi < 2; mi++)
#pragma unroll
            for (int nf = 0; nf < 8; nf++)
#pragma unroll
                for (int q = 0; q < 4; q++) acc[mi][nf][q] = 0.0f;

        for (int kk = 0; kk < NKCH; kk++) {
            if (kk < NKCH - 1) {
                loadChunk(tid, m0, n0, kk + 1, aS[(kk + 1) & 1], bS[(kk + 1) & 1]);
                cp_wait1();
            } else {
                cp_wait0();
            }
            __syncthreads();

            uint32_t ab = aS[kk & 1];
            uint32_t bb = bS[kk & 1];
#pragma unroll
            for (int ks = 0; ks < 4; ks++) {
                uint32_t a[2][4], b[4][4];
                ldsm4(a[0], ab + aOff[0][ks]);
                ldsm4(a[1], ab + aOff[1][ks]);
#pragma unroll
                for (int nf2 = 0; nf2 < 4; nf2++) ldsm4(b[nf2], bb + bOff[nf2][ks]);
#pragma unroll
                for (int mi = 0; mi < 2; mi++)
#pragma unroll
                    for (int nf2 = 0; nf2 < 4; nf2++) {
                        mma16816(acc[mi][nf2 * 2],     a[mi], b[nf2][0], b[nf2][2]);
                        mma16816(acc[mi][nf2 * 2 + 1], a[mi], b[nf2][1], b[nf2][3]);
                    }
            }
            __syncthreads();
        }

        // prefetch next tile's chunk 0 (overlaps epilogue)
        {
            int nt = tile + NCTA;
            if (nt < NTILES)
                loadChunk(tid, (nt & 15) * BM, (nt >> 4) * BN, 0, aS[0], bS[0]);
        }

        // ---- epilogue: bias add, exp for Z (split MUFU/FMA), fp16 logit staging ----
        const int vrem = VOC - n0;
        const int rA0 = wm * 32 + (lane >> 2);
#pragma unroll
        for (int mi = 0; mi < 2; mi++) {
            const int rA = rA0 + mi * 16;
            const int rB = rA + 8;
            float sA = 0.0f, sB = 0.0f;
#pragma unroll
            for (int nf = 0; nf < 8; nf++) {
                const int cl = wn * 64 + nf * 8 + (lane & 3) * 2;
                const float bi0 = s_bias[cl], bi1 = s_bias[cl + 1];
                float lA0 = acc[mi][nf][0] + bi0, lA1 = acc[mi][nf][1] + bi1;
                float lB0 = acc[mi][nf][2] + bi0, lB1 = acc[mi][nf][3] + bi1;
                float eA0 = __expf(lA0), eA1 = pexp(lA1);
                float eB0 = __expf(lB0), eB1 = pexp(lB1);
                if (n0 == 0) {
                    if (cl == 0) { g_e0v[m0 + rA] = eA0; g_e0v[m0 + rB] = eB0; }
                    if (cl == 4) {
                        g_copyv[m0 + rA] = 1.0f / (1.0f + __expf(-lA0));
                        g_copyv[m0 + rB] = 1.0f / (1.0f + __expf(-lB0));
                        eA0 = 0.0f; eB0 = 0.0f;             // COPY masked from softmax
                    }
                }
                if (cl     >= vrem) { eA0 = 0.0f; eB0 = 0.0f; }
                if (cl + 1 >= vrem) { eA1 = 0.0f; eB1 = 0.0f; }
                sA += eA0 + eA1;  sB += eB0 + eB1;
                const int p = cl >> 1;
                __half2 hA = __floats2half2_rn(lA0, lA1);   // store LOGITS
                __half2 hB = __floats2half2_rn(lB0, lB1);
                stg32[rA * STGPITCH + p] = *(uint32_t*)&hA;
                stg32[rB * STGPITCH + p] = *(uint32_t*)&hB;
            }
            sA += __shfl_xor_sync(0xFFFFFFFFu, sA, 1);
            sA += __shfl_xor_sync(0xFFFFFFFFu, sA, 2);
            sB += __shfl_xor_sync(0xFFFFFFFFu, sB, 1);
            sB += __shfl_xor_sync(0xFFFFFFFFu, sB, 2);
            if ((lane & 3) == 0) {
                atomicAdd(&s_zrow[rA], sA);
                atomicAdd(&s_zrow[rB], sB);
            }
        }
        __syncthreads();

        // coalesced copy-out: 128 rows x 16 uint4 (tail tile: 10 = 80 halves)
        const int segs = (vrem >= 128) ? 16 : 10;
#pragma unroll 4
        for (int f = tid; f < 2048; f += 256) {
            int r = f >> 4, s = f & 15;
            if (s < segs) {
                uint4 v = *(uint4*)(stg32 + r * STGPITCH + s * 4);
                ((uint4*)(g_logit + (size_t)(m0 + r) * VOC + n0))[s] = v;
            }
        }
        if (tid < 128) {
            g_Zp[(size_t)(m0 + tid) * NTN + j] = s_zrow[tid];
            s_zrow[tid] = 0.0f;
        }
        __syncthreads();
    }
}

// ---------------- kernel 3: per-row params (Z, norm, scatter dedup) ----------------
__global__ void __launch_bounds__(64) rowparams_kernel(const float* __restrict__ attn,
                                                       const int* __restrict__ src,
                                                       const int* __restrict__ alignment) {
    __shared__ float s_red[64];
    __shared__ float s_attn[SLEN];
    __shared__ int   s_idx[SLEN];
    __shared__ float s_c, s_norm;

    const int r = blockIdx.x, t = threadIdx.x;
    float z = 0.0f;
    for (int j = t; j < NTN; j += 64) z += g_Zp[(size_t)r * NTN + j];
    s_red[t] = z;
    __syncthreads();
    for (int o = 32; o > 0; o >>= 1) {
        if (t < o) s_red[t] += s_red[t + o];
        __syncthreads();
    }
    if (t < SLEN) {
        s_attn[t] = attn[r * SLEN + t];
        int bb = r % BATCH;
        s_idx[t] = alignment[src[bb * SLEN + t]];
    }
    __syncthreads();
    if (t == 0) {
        float Z  = s_red[0];
        float c  = g_copyv[r];
        float e0 = g_e0v[r];
        float sa = 0.0f, A0 = 0.0f;
        for (int s = 0; s < SLEN; s++) {
            sa += s_attn[s];
            if (s_idx[s] == 0) A0 += s_attn[s];
        }
        float norm = EPSV + (1.0f - c) * (1.0f - e0 / Z) + c * (sa - A0);
        s_c = c; s_norm = norm;
        float s1 = (1.0f - c) / (Z * norm);
        float padv = logf(EPSV / norm + EPSV);
        g_rowp[r] = make_float4(s1, padv, logf(s1), 0.0f);
    }
    __syncthreads();
    if (t < SLEN) {
        int idx = s_idx[t];
        int owner = (idx != 0);
        float sum = 0.0f;
        for (int s = 0; s < SLEN; s++) {
            if (s_idx[s] == idx) {
                if (s < t) owner = 0;
                sum += s_attn[s];
            }
        }
        if (owner) {
            g_fixc[r * SLEN + t] = idx;
            g_fixv[r * SLEN + t] = s_c * sum / s_norm;
        } else {
            g_fixc[r * SLEN + t] = -1;
        }
    }
}

// ---------------- kernel 4: final output (pure streaming add) + fix-ups ----------------
__global__ void __launch_bounds__(512) final_kernel(float* __restrict__ out) {
    const int r = blockIdx.x;
    const float4 rp = g_rowp[r];
    const float C = rp.z;                        // log(s1)
    const size_t base = (size_t)r * VOC;
    const uint2* ep = (const uint2*)(g_logit + base);   // 4 halves per load
    float4* o4 = (float4*)(out + base);

#pragma unroll 4
    for (int p = threadIdx.x; p < VOC / 4; p += 512) {
        uint2 pk = __ldcs(&ep[p]);
        __half2 h0 = *(__half2*)&pk.x, h1 = *(__half2*)&pk.y;
        float2 f0 = __half22float2(h0), f1 = __half22float2(h1);
        float4 v = make_float4(f0.x + C, f0.y + C, f1.x + C, f1.y + C);
        __stcs(&o4[p], v);
    }
    __syncthreads();
    const int t = threadIdx.x;
    if (t == 0) out[base + 4] = LOG_EPS;         // COPY default (overwritten if scattered)
    if (t == 1) out[base + 0] = rp.y;            // PAD
    __syncthreads();
    if (t < SLEN) {
        int cidx = g_fixc[r * SLEN + t];
        if (cidx >= 0) {
            float l = __half2float(g_logit[base + cidx]);
            float e = (cidx == 4) ? 0.0f : __expf(l);
            float v = fmaf(e, rp.x, g_fixv[r * SLEN + t] + EPSV);
            out[base + cidx] = logf(v);
        }
    }
}

// ---------------- launch ----------------
extern "C" void kernel_launch(void* const* d_in, const int* in_sizes, int n_in,
                              void* d_out, int out_size) {
    const float* hidden    = (const float*)d_in[0];
    const float* attn      = (const float*)d_in[1];
    const float* W         = (const float*)d_in[2];
    const float* b         = (const float*)d_in[3];
    const int*   src       = (const int*)d_in[4];
    const int*   alignment = (const int*)d_in[5];
    float* out = (float*)d_out;

    // pad(1K) + A stages(32K) + B stages(32K) + staging(34K) = ~99 KB -> 2 CTAs/SM
    const int dyn_smem = 1024 + 32768 + 32768 + 34816;
    cudaFuncSetAttribute(gemm_kernel, cudaFuncAttributeMaxDynamicSharedMemorySize, dyn_smem);

    prep_kernel<<<25000, 256>>>((const float4*)W, (const float4*)hidden);
    gemm_kernel<<<NCTA, 256, dyn_smem>>>(b);
    rowparams_kernel<<<TBROWS, 64>>>(attn, src, alignment);
    final_kernel<<<TBROWS, 512>>>(out);
}